// round 7
// baseline (speedup 1.0000x reference)
#include <cuda_runtime.h>
#include <cuda_bf16.h>

#define B 16
#define H 512
#define W 512
#define IMG (H*W)
#define KER 31
#define PAD 15
#define WPR 16                  // u32 words per row of packed mask bits

// Scratch (device globals)
__device__ unsigned int  g_bits[B*H*WPR];     // packed mask bits
__device__ double        g_acc [B][4];        // [weit_sum, wbce_sum, inter, card]

// ---------------------------------------------------------------------------
// K1: pack mask bits only (int4 + shfl-OR). grid (H/4, B), block 512.
// ---------------------------------------------------------------------------
__global__ void __launch_bounds__(512) k1_pack(const int* __restrict__ mask)
{
    const int t   = threadIdx.x;
    const int rib = t >> 7;           // row in block 0..3
    const int q   = t & 127;          // column quad (cols 4q..4q+3)
    const int r   = blockIdx.x*4 + rib;
    const int b   = blockIdx.y;

    if (blockIdx.x == 0 && blockIdx.y == 0 && t < B*4)
        ((double*)g_acc)[t] = 0.0;

    const int4 mv = ((const int4*)mask)[(b*H + r)*(W/4) + q];
    const int m0 = (mv.x == 255) ? 0 : mv.x;
    const int m1 = (mv.y == 255) ? 0 : mv.y;
    const int m2 = (mv.z == 255) ? 0 : mv.z;
    const int m3 = (mv.w == 255) ? 0 : mv.w;
    unsigned int nib = (m0 ? 1u : 0u) | (m1 ? 2u : 0u) | (m2 ? 4u : 0u) | (m3 ? 8u : 0u);

    const int lane = t & 31;
    unsigned int v = nib << ((lane & 7) * 4);
    v |= __shfl_xor_sync(0xffffffffu, v, 1);
    v |= __shfl_xor_sync(0xffffffffu, v, 2);
    v |= __shfl_xor_sync(0xffffffffu, v, 4);
    if ((lane & 7) == 0)
        g_bits[(b*H + r)*WPR + (q >> 3)] = v;
}

// ---------------------------------------------------------------------------
// K2: stage bits in smem, on-the-fly hsum popcounts, vertical running sum,
//     fused loss math. grid (1, H/ROWS, B), block 256, 2 cols/thread.
// ---------------------------------------------------------------------------
#define ROWS 32
#define SROWS (ROWS + 31)       // 63 staged rows (logical r0-15 .. r0+ROWS+15)
#define SW 20                   // smem row stride: [0]=0, [1..16]=data, [17..19]=0

__device__ __forceinline__ int hwin(const unsigned int* row, int ws, int sh)
{
    const unsigned int lo = row[ws];
    const unsigned int hi = row[ws + 1];
    return __popc(__funnelshift_r(lo, hi, sh) & 0x7FFFFFFFu);
}

__global__ void __launch_bounds__(256) k2_main(const float* __restrict__ pred)
{
    __shared__ unsigned int sw[SROWS][SW];
    const int tid = threadIdx.x;
    const int c0  = tid * 2;
    const int r0  = blockIdx.y * ROWS;
    const int b   = blockIdx.z;

    // cooperative staged load of packed bits, zero-padded halo
    for (int i = tid; i < SROWS*SW; i += 256) {
        const int rr = i / SW, w = i % SW;
        const int r = r0 - PAD + rr;
        unsigned int val = 0;
        if (w >= 1 && w <= WPR && r >= 0 && r < H)
            val = g_bits[(b*H + r)*WPR + (w - 1)];
        sw[rr][w] = val;
    }
    __syncthreads();

    // fixed per-column window params (padded bit position s = c + 32 - 15)
    const int s0 = c0 + 17, ws0 = s0 >> 5, sh0 = s0 & 31;
    const int s1 = c0 + 18, ws1 = s1 >> 5, sh1 = s1 & 31;
    const int mw = 1 + (c0 >> 5), msh = c0 & 31;

    const float* p0p = pred + (size_t)(2*b)*IMG + c0;
    const float* p1p = p0p + IMG;

    // init vertical window: logical rows r0-15..r0+15 == staged rows 0..30
    int v0 = 0, v1 = 0;
    #pragma unroll
    for (int j = 0; j < KER; ++j) {
        v0 += hwin(sw[j], ws0, sh0);
        v1 += hwin(sw[j], ws1, sh1);
    }

    float a_w = 0.f, a_wb = 0.f, a_i = 0.f, a_c = 0.f;

    #pragma unroll 4
    for (int rr = 0; rr < ROWS; ++rr) {
        const int r = r0 + rr;
        const unsigned int wbits = sw[rr + PAD][mw];
        const float2 f0 = *(const float2*)&p0p[r*W];
        const float2 f1 = *(const float2*)&p1p[r*W];

        #pragma unroll
        for (int j = 0; j < 2; ++j) {
            const int   vs = j ? v1 : v0;
            const float pooled = (float)vs * (1.0f/961.0f);
            const float mf = (float)((wbits >> (msh + j)) & 1u);
            const float weit = 1.0f + 5.0f * fabsf(pooled - mf);

            const float d = (j ? f1.y : f1.x) - (j ? f0.y : f0.x);
            const float e = __expf(-fabsf(d));
            const float tl = __logf(1.0f + e);
            const float wbce = fmaxf((mf != 0.f) ? -d : d, 0.0f) + tl;
            const float p1 = ((d >= 0.f) ? 1.0f : e) * __fdividef(1.0f, 1.0f + e);

            a_w  += weit;
            a_wb += weit * wbce;
            a_i  += p1 * mf * weit;
            a_c  += (p1 + mf) * weit;
        }
        // slide: add logical r+16 (staged rr+31), drop logical r-15 (staged rr)
        v0 += hwin(sw[rr + 31], ws0, sh0) - hwin(sw[rr], ws0, sh0);
        v1 += hwin(sw[rr + 31], ws1, sh1) - hwin(sw[rr], ws1, sh1);
    }

    #pragma unroll
    for (int off = 16; off > 0; off >>= 1) {
        a_w  += __shfl_down_sync(0xffffffffu, a_w,  off);
        a_wb += __shfl_down_sync(0xffffffffu, a_wb, off);
        a_i  += __shfl_down_sync(0xffffffffu, a_i,  off);
        a_c  += __shfl_down_sync(0xffffffffu, a_c,  off);
    }
    if ((tid & 31) == 0) {
        atomicAdd(&g_acc[b][0], (double)a_w);
        atomicAdd(&g_acc[b][1], (double)a_wb);
        atomicAdd(&g_acc[b][2], (double)a_i);
        atomicAdd(&g_acc[b][3], (double)a_c);
    }
}

// ---------------------------------------------------------------------------
// K3: combine per-batch losses -> scalar mean
// ---------------------------------------------------------------------------
__global__ void k3_final(float* __restrict__ out)
{
    const int b = threadIdx.x;
    double loss = 0.0;
    if (b < B) {
        const double w  = g_acc[b][0];
        const double wb = g_acc[b][1];
        const double it = g_acc[b][2];
        const double cd = g_acc[b][3];
        const double un = cd - it;
        loss = wb / w + (1.0 - (it + 1.0) / (un + 1.0));
    }
    #pragma unroll
    for (int off = 16; off > 0; off >>= 1)
        loss += __shfl_down_sync(0xffffffffu, loss, off);
    if (b == 0) out[0] = (float)(loss / (double)B);
}

extern "C" void kernel_launch(void* const* d_in, const int* in_sizes, int n_in,
                              void* d_out, int out_size)
{
    const float* pred;
    const int*   mask;
    if (in_sizes[0] == 2*B*IMG) {
        pred = (const float*)d_in[0];
        mask = (const int*)d_in[1];
    } else {
        pred = (const float*)d_in[1];
        mask = (const int*)d_in[0];
    }
    float* out = (float*)d_out;
    (void)n_in; (void)out_size;

    k1_pack<<<dim3(H/4, B), 512>>>(mask);
    k2_main<<<dim3(1, H/ROWS, B), 256>>>(pred);
    k3_final<<<1, 32>>>(out);
}

// round 8
// speedup vs baseline: 1.0380x; 1.0380x over previous
#include <cuda_runtime.h>
#include <cuda_bf16.h>

#define B 16
#define H 512
#define W 512
#define IMG (H*W)
#define KER 31
#define PAD 15
#define WPR 16                  // u32 words per row of packed mask bits

// Scratch (device globals)
__device__ unsigned int  g_bits[B*H*WPR];     // packed mask bits
__device__ double        g_acc [B][4];        // [weit_sum, wbce_sum, inter, card]

// ---------------------------------------------------------------------------
// K1: pack mask bits only (int4 + shfl-OR). grid (H/4, B), block 512.
// ---------------------------------------------------------------------------
__global__ void __launch_bounds__(512) k1_pack(const int* __restrict__ mask)
{
    const int t   = threadIdx.x;
    const int rib = t >> 7;           // row in block 0..3
    const int q   = t & 127;          // column quad (cols 4q..4q+3)
    const int r   = blockIdx.x*4 + rib;
    const int b   = blockIdx.y;

    if (blockIdx.x == 0 && blockIdx.y == 0 && t < B*4)
        ((double*)g_acc)[t] = 0.0;

    const int4 mv = ((const int4*)mask)[(b*H + r)*(W/4) + q];
    const int m0 = (mv.x == 255) ? 0 : mv.x;
    const int m1 = (mv.y == 255) ? 0 : mv.y;
    const int m2 = (mv.z == 255) ? 0 : mv.z;
    const int m3 = (mv.w == 255) ? 0 : mv.w;
    unsigned int nib = (m0 ? 1u : 0u) | (m1 ? 2u : 0u) | (m2 ? 4u : 0u) | (m3 ? 8u : 0u);

    const int lane = t & 31;
    unsigned int v = nib << ((lane & 7) * 4);
    v |= __shfl_xor_sync(0xffffffffu, v, 1);
    v |= __shfl_xor_sync(0xffffffffu, v, 2);
    v |= __shfl_xor_sync(0xffffffffu, v, 4);
    if ((lane & 7) == 0)
        g_bits[(b*H + r)*WPR + (q >> 3)] = v;
}

// ---------------------------------------------------------------------------
// K2: stage bits in smem, on-the-fly hsum popcounts, vertical running sum,
//     fused loss math. grid (1, H/ROWS, B), block 256, 2 cols/thread.
// ---------------------------------------------------------------------------
#define ROWS 32
#define SROWS (ROWS + 31)       // 63 staged rows (logical r0-15 .. r0+ROWS+15)
#define SW 20                   // smem row stride: [0]=0, [1..16]=data, [17..19]=0

__device__ __forceinline__ int hwin(const unsigned int* row, int ws, int sh)
{
    const unsigned int lo = row[ws];
    const unsigned int hi = row[ws + 1];
    return __popc(__funnelshift_r(lo, hi, sh) & 0x7FFFFFFFu);
}

__global__ void __launch_bounds__(256) k2_main(const float* __restrict__ pred)
{
    __shared__ unsigned int sw[SROWS][SW];
    const int tid = threadIdx.x;
    const int c0  = tid * 2;
    const int r0  = blockIdx.y * ROWS;
    const int b   = blockIdx.z;

    // cooperative staged load of packed bits, zero-padded halo
    for (int i = tid; i < SROWS*SW; i += 256) {
        const int rr = i / SW, w = i % SW;
        const int r = r0 - PAD + rr;
        unsigned int val = 0;
        if (w >= 1 && w <= WPR && r >= 0 && r < H)
            val = g_bits[(b*H + r)*WPR + (w - 1)];
        sw[rr][w] = val;
    }
    __syncthreads();

    // fixed per-column window params (padded bit position s = c + 32 - 15)
    const int s0 = c0 + 17, ws0 = s0 >> 5, sh0 = s0 & 31;
    const int s1 = c0 + 18, ws1 = s1 >> 5, sh1 = s1 & 31;
    const int mw = 1 + (c0 >> 5), msh = c0 & 31;

    const float* p0p = pred + (size_t)(2*b)*IMG + c0;
    const float* p1p = p0p + IMG;

    // init vertical window: logical rows r0-15..r0+15 == staged rows 0..30
    int v0 = 0, v1 = 0;
    #pragma unroll
    for (int j = 0; j < KER; ++j) {
        v0 += hwin(sw[j], ws0, sh0);
        v1 += hwin(sw[j], ws1, sh1);
    }

    float a_w = 0.f, a_wb = 0.f, a_i = 0.f, a_c = 0.f;

    #pragma unroll 4
    for (int rr = 0; rr < ROWS; ++rr) {
        const int r = r0 + rr;
        const unsigned int wbits = sw[rr + PAD][mw];
        const float2 f0 = *(const float2*)&p0p[r*W];
        const float2 f1 = *(const float2*)&p1p[r*W];

        #pragma unroll
        for (int j = 0; j < 2; ++j) {
            const int   vs = j ? v1 : v0;
            const float pooled = (float)vs * (1.0f/961.0f);
            const float mf = (float)((wbits >> (msh + j)) & 1u);
            const float weit = 1.0f + 5.0f * fabsf(pooled - mf);

            const float d = (j ? f1.y : f1.x) - (j ? f0.y : f0.x);
            const float e = __expf(-fabsf(d));
            const float tl = __logf(1.0f + e);
            const float wbce = fmaxf((mf != 0.f) ? -d : d, 0.0f) + tl;
            const float p1 = ((d >= 0.f) ? 1.0f : e) * __fdividef(1.0f, 1.0f + e);

            a_w  += weit;
            a_wb += weit * wbce;
            a_i  += p1 * mf * weit;
            a_c  += (p1 + mf) * weit;
        }
        // slide: add logical r+16 (staged rr+31), drop logical r-15 (staged rr)
        v0 += hwin(sw[rr + 31], ws0, sh0) - hwin(sw[rr], ws0, sh0);
        v1 += hwin(sw[rr + 31], ws1, sh1) - hwin(sw[rr], ws1, sh1);
    }

    #pragma unroll
    for (int off = 16; off > 0; off >>= 1) {
        a_w  += __shfl_down_sync(0xffffffffu, a_w,  off);
        a_wb += __shfl_down_sync(0xffffffffu, a_wb, off);
        a_i  += __shfl_down_sync(0xffffffffu, a_i,  off);
        a_c  += __shfl_down_sync(0xffffffffu, a_c,  off);
    }
    if ((tid & 31) == 0) {
        atomicAdd(&g_acc[b][0], (double)a_w);
        atomicAdd(&g_acc[b][1], (double)a_wb);
        atomicAdd(&g_acc[b][2], (double)a_i);
        atomicAdd(&g_acc[b][3], (double)a_c);
    }
}

// ---------------------------------------------------------------------------
// K3: combine per-batch losses -> scalar mean
// ---------------------------------------------------------------------------
__global__ void k3_final(float* __restrict__ out)
{
    const int b = threadIdx.x;
    double loss = 0.0;
    if (b < B) {
        const double w  = g_acc[b][0];
        const double wb = g_acc[b][1];
        const double it = g_acc[b][2];
        const double cd = g_acc[b][3];
        const double un = cd - it;
        loss = wb / w + (1.0 - (it + 1.0) / (un + 1.0));
    }
    #pragma unroll
    for (int off = 16; off > 0; off >>= 1)
        loss += __shfl_down_sync(0xffffffffu, loss, off);
    if (b == 0) out[0] = (float)(loss / (double)B);
}

extern "C" void kernel_launch(void* const* d_in, const int* in_sizes, int n_in,
                              void* d_out, int out_size)
{
    const float* pred;
    const int*   mask;
    if (in_sizes[0] == 2*B*IMG) {
        pred = (const float*)d_in[0];
        mask = (const int*)d_in[1];
    } else {
        pred = (const float*)d_in[1];
        mask = (const int*)d_in[0];
    }
    float* out = (float*)d_out;
    (void)n_in; (void)out_size;

    k1_pack<<<dim3(H/4, B), 512>>>(mask);
    k2_main<<<dim3(1, H/ROWS, B), 256>>>(pred);
    k3_final<<<1, 32>>>(out);
}